// round 15
// baseline (speedup 1.0000x reference)
#include <cuda_runtime.h>
#include <cuda_bf16.h>
#include <cstdint>
#include <math.h>

// Shapes: support [5,196,384], query [512,196,384], out [1,512,5]
#define NC 5
#define M_IMG 512
#define P 196
#define D 384

#define NEG_BIG (-1.0e30f)

#define SROWS 256           // padded support rows per class in g_sbf (zero-init)
#define BROWS 224           // resident support rows (28 n8 tiles, uniform 7/warp)
#define NT8 28              // support n8 tiles
#define A_CH_ROWS 32        // query chunk rows (2 m16 tiles)
#define NCHUNK 7            // chunks 0..5 use 2 m16; chunk 6 computes 1 m16 (rows 192..207)

#define B_KT_STRIDE (BROWS * 128)     // 28672 B per k-tile
#define A_KT_STRIDE (A_CH_ROWS * 128) // 4096  B per k-tile
#define A_BUF_SIZE (A_CH_ROWS * 768)  // 24576 B per chunk buffer

// smem layout: [0..3584) pmax4[4][224] | [4096..53248) A bufs x2 | [53248..225280) B
#define SM_PM 0
#define SM_A 4096
#define SM_B 53248
#define SM_TOTAL 225280

#define THREADS 128

// ---------------- staged data (allocation-free: __device__ globals) -----------
// query: raw bf16 (+64 zero pad rows: chunk loads reach row 223 for m=511)
__device__ __align__(16) __nv_bfloat16 g_qbf[(M_IMG * P + 64) * D];
// support: L2-normalized bf16, padded to 256 rows/class (pad rows stay zero)
__device__ __align__(16) __nv_bfloat16 g_sbf[NC * SROWS * D];
// inverse L2 norm of each query row
__device__ float g_invq[M_IMG * P];

// ---------------- PTX helpers -------------------------------------------------
__device__ __forceinline__ uint32_t smem_u32(const void* p) {
    uint32_t a;
    asm("{ .reg .u64 t; cvta.to.shared.u64 t, %1; cvt.u32.u64 %0, t; }" : "=r"(a) : "l"(p));
    return a;
}
#define SW128(o) ((o) ^ (((o) >> 3) & 0x70))

__device__ __forceinline__ void cp_async16(uint32_t dst, const void* src) {
    asm volatile("cp.async.cg.shared.global [%0], [%1], 16;" :: "r"(dst), "l"(src));
}
__device__ __forceinline__ void cp_commit() { asm volatile("cp.async.commit_group;" ::: "memory"); }
template <int N>
__device__ __forceinline__ void cp_wait_n() {
    asm volatile("cp.async.wait_group %0;" :: "n"(N) : "memory");
}

#define LDSM_X4(r, addr) \
    asm volatile("ldmatrix.sync.aligned.m8n8.x4.shared.b16 {%0,%1,%2,%3}, [%4];" \
        : "=r"((r)[0]), "=r"((r)[1]), "=r"((r)[2]), "=r"((r)[3]) : "r"(addr))

#define LDSM_X2(r0, r1, addr) \
    asm volatile("ldmatrix.sync.aligned.m8n8.x2.shared.b16 {%0,%1}, [%2];" \
        : "=r"(r0), "=r"(r1) : "r"(addr))

#define MMA16816(c, a, b0, b1) \
    asm volatile("mma.sync.aligned.m16n8k16.row.col.f32.bf16.bf16.f32 " \
        "{%0,%1,%2,%3}, {%4,%5,%6,%7}, {%8,%9}, {%0,%1,%2,%3};" \
        : "+f"((c)[0]), "+f"((c)[1]), "+f"((c)[2]), "+f"((c)[3]) \
        : "r"((a)[0]), "r"((a)[1]), "r"((a)[2]), "r"((a)[3]), "r"(b0), "r"(b1))

// ---------------- Kernel 1: norms + bf16 staging ------------------------------
__global__ void stage_kernel(const float* __restrict__ support,
                             const float* __restrict__ query) {
    const int warp = (blockIdx.x * blockDim.x + threadIdx.x) >> 5;
    const int lane = threadIdx.x & 31;
    const int nq = M_IMG * P;
    const int nrows = nq + NC * P;
    if (warp >= nrows) return;

    const bool is_q = (warp < nq);
    const float* src = is_q ? (query + (size_t)warp * D)
                            : (support + (size_t)(warp - nq) * D);

    float4 v[3];
    float s = 0.0f;
    #pragma unroll
    for (int j = 0; j < 3; ++j) {
        v[j] = reinterpret_cast<const float4*>(src)[lane + 32 * j];
        s += v[j].x * v[j].x + v[j].y * v[j].y + v[j].z * v[j].z + v[j].w * v[j].w;
    }
    #pragma unroll
    for (int off = 16; off; off >>= 1) s += __shfl_xor_sync(0xffffffffu, s, off);
    const float inv = 1.0f / fmaxf(sqrtf(s), 1e-12f);

    if (is_q) {
        uint32_t* dst = reinterpret_cast<uint32_t*>(g_qbf + (size_t)warp * D);
        #pragma unroll
        for (int j = 0; j < 3; ++j) {
            const int k = lane + 32 * j;
            __nv_bfloat162 a = __floats2bfloat162_rn(v[j].x, v[j].y);
            __nv_bfloat162 b = __floats2bfloat162_rn(v[j].z, v[j].w);
            dst[2 * k]     = *reinterpret_cast<uint32_t*>(&a);
            dst[2 * k + 1] = *reinterpret_cast<uint32_t*>(&b);
        }
        if (lane == 0) g_invq[warp] = inv;
    } else {
        const int sr = warp - nq;
        const int c = sr / P, p = sr % P;
        uint32_t* dst = reinterpret_cast<uint32_t*>(g_sbf + ((size_t)c * SROWS + p) * D);
        #pragma unroll
        for (int j = 0; j < 3; ++j) {
            const int k = lane + 32 * j;
            __nv_bfloat162 a = __floats2bfloat162_rn(v[j].x * inv, v[j].y * inv);
            __nv_bfloat162 b = __floats2bfloat162_rn(v[j].z * inv, v[j].w * inv);
            dst[2 * k]     = *reinterpret_cast<uint32_t*>(&a);
            dst[2 * k + 1] = *reinterpret_cast<uint32_t*>(&b);
        }
    }
}

// ---------------- per-k-tile GEMM bodies (uniform across warps) ----------------
// A = query chunk m16 tiles, B = support n8 tiles t = w + 4i, i<7 (all 28 valid).
// B fetched via paired ldmatrix.x4: one instruction loads tiles (w+8j, w+8j+4)
// complete (both k-halves) using 4 independent 8-lane base addresses.
__device__ __forceinline__ void gemm_kt_mt2(uint32_t abase, uint32_t bbase,
                                            int w, int lane, float (&cacc)[2][7][4]) {
    const int l7 = lane & 7;
    const int a_row = (((lane >> 3) & 1) << 3) + l7;
    const int a_kb  = ((lane >> 4) & 1) << 4;
    const int sel16 = ((lane >> 3) & 1) << 4;          // +16B for k 8..15
    const int tsel  = (lane >> 4) & 1;                 // x4: second tile of pair
    #pragma unroll
    for (int k16 = 0; k16 < 4; ++k16) {
        const int kb = k16 * 32;
        uint32_t a[2][4];
        LDSM_X4(a[0], abase + SW128(a_row * 128 + kb + a_kb));
        LDSM_X4(a[1], abase + SW128((16 + a_row) * 128 + kb + a_kb));
        uint32_t b[7][2];
        #pragma unroll
        for (int j = 0; j < 3; ++j) {                  // pairs (i=2j, 2j+1)
            const int t = w + 8 * j + 4 * tsel;
            LDSM_X4(&b[2 * j][0],                      // b[2j][0..1], b[2j+1][0..1]
                    bbase + SW128((t * 8 + l7) * 128 + kb + sel16));
        }
        {                                              // leftover i=6
            const int t = w + 24;
            LDSM_X2(b[6][0], b[6][1],
                    bbase + SW128((t * 8 + l7) * 128 + kb + sel16));
        }
        #pragma unroll
        for (int mt = 0; mt < 2; ++mt)
            #pragma unroll
            for (int i = 0; i < 7; ++i)
                MMA16816(cacc[mt][i], a[mt], b[i][0], b[i][1]);
    }
}

// tail chunk: one m16 tile (rows 192..207). Same B pairing, half the A work.
__device__ __forceinline__ void gemm_kt_mt1(uint32_t abase, uint32_t bbase,
                                            int w, int lane, float (&cacc)[2][7][4]) {
    const int l7 = lane & 7;
    const int a_row = (((lane >> 3) & 1) << 3) + l7;
    const int a_kb  = ((lane >> 4) & 1) << 4;
    const int sel16 = ((lane >> 3) & 1) << 4;
    const int tsel  = (lane >> 4) & 1;
    #pragma unroll
    for (int k16 = 0; k16 < 4; ++k16) {
        const int kb = k16 * 32;
        uint32_t a[4];
        LDSM_X4(a, abase + SW128(a_row * 128 + kb + a_kb));
        uint32_t b[7][2];
        #pragma unroll
        for (int j = 0; j < 3; ++j) {
            const int t = w + 8 * j + 4 * tsel;
            LDSM_X4(&b[2 * j][0],
                    bbase + SW128((t * 8 + l7) * 128 + kb + sel16));
        }
        {
            const int t = w + 24;
            LDSM_X2(b[6][0], b[6][1],
                    bbase + SW128((t * 8 + l7) * 128 + kb + sel16));
        }
        #pragma unroll
        for (int i = 0; i < 7; ++i)
            MMA16816(cacc[0][i], a, b[i][0], b[i][1]);
    }
}

// chunk-0 k-tile loop with incremental B waits (literal wait_group immediates).
// Pending after prologue commits: {A0, B0..B5, A1}. At step KT we need
// A0 + B0..BKT -> allowed pending = (5-KT) B groups + A1 = 6-KT.
template <int KT>
__device__ __forceinline__ void chunk0_loop(uint32_t abase0, uint32_t bbase0,
                                            int w, int lane, float (&cacc)[2][7][4]) {
    if constexpr (KT < 6) {
        cp_wait_n<6 - KT>();
        __syncthreads();
        gemm_kt_mt2(abase0 + KT * A_KT_STRIDE, bbase0 + KT * B_KT_STRIDE,
                    w, lane, cacc);
        chunk0_loop<KT + 1>(abase0, bbase0, w, lane, cacc);
    }
}

// ---------------- Kernel 2: support-resident fused HMMA + max + top6 ----------
__global__ __launch_bounds__(THREADS, 1)
void protonet_hmma_kernel(const float* __restrict__ scale_cls,
                          const float* __restrict__ bias,
                          float* __restrict__ out) {
    extern __shared__ char sm[];
    const uint32_t smb = smem_u32(sm);
    float* pmax4 = reinterpret_cast<float*>(sm + SM_PM);   // [4][224]
    const int tid = threadIdx.x;
    const int w = tid >> 5;
    const int lane = tid & 31;
    const int c = blockIdx.x;     // class fast -> query chunk L2 reuse
    const int m = blockIdx.y;

    const __nv_bfloat16* qbase = g_qbf + (size_t)m * P * D;
    const __nv_bfloat16* sbase = g_sbf + (size_t)c * SROWS * D;

    // query chunk loader: ALWAYS 32 rows x 384 cols, compile-time strides.
    // Chunk 6 loads 16 garbage pad rows beyond 207 -- harmless, never computed on.
    auto stage_a = [&](int ch, int buf) {
        const uint32_t abase = smb + SM_A + buf * A_BUF_SIZE;
        #pragma unroll
        for (int idx = tid; idx < A_CH_ROWS * 8 * 6; idx += THREADS) {  // 1536 x 16B
            const int kt  = idx >> 8;              // /(32*8), compile-time shift
            const int rem = idx & 255;
            const int row = rem >> 3;
            const int cb  = (rem & 7) << 4;
            const void* src = qbase + (size_t)(ch * A_CH_ROWS + row) * D + kt * 64 + (cb >> 1);
            cp_async16(abase + kt * A_KT_STRIDE + SW128(row * 128 + cb), src);
        }
        cp_commit();
    };

    // prologue: A0 (1 group), B as 6 per-k-tile groups, A1 (1 group)
    stage_a(0, 0);
    #pragma unroll
    for (int kt = 0; kt < 6; ++kt) {
        for (int idx = tid; idx < BROWS * 8; idx += THREADS) {   // 1792 x 16B
            const int row = idx >> 3;
            const int cb  = (idx & 7) << 4;
            const void* src = sbase + (size_t)row * D + kt * 64 + (cb >> 1);
            cp_async16(smb + SM_B + kt * B_KT_STRIDE + SW128(row * 128 + cb), src);
        }
        cp_commit();
    }
    stage_a(1, 1);

    // fold + write per-warp partials for a finished 32-row chunk
    auto finish_chunk = [&](int ch, float (&cc)[2][7][4]) {
        float rmax[2][2];
        rmax[0][0] = rmax[0][1] = rmax[1][0] = rmax[1][1] = NEG_BIG;
        #pragma unroll
        for (int i = 0; i < 7; ++i) {
            const int col0 = (w + 4 * i) * 8 + ((lane & 3) << 1);
            if (col0 < P) {   // support col pair valid (196 is even)
                #pragma unroll
                for (int mt = 0; mt < 2; ++mt) {
                    rmax[mt][0] = fmaxf(rmax[mt][0], fmaxf(cc[mt][i][0], cc[mt][i][1]));
                    rmax[mt][1] = fmaxf(rmax[mt][1], fmaxf(cc[mt][i][2], cc[mt][i][3]));
                }
            }
        }
        #pragma unroll
        for (int mt = 0; mt < 2; ++mt) {
            float v0 = rmax[mt][0], v1 = rmax[mt][1];
            #pragma unroll
            for (int off = 1; off <= 2; off <<= 1) {
                v0 = fmaxf(v0, __shfl_xor_sync(0xffffffffu, v0, off));
                v1 = fmaxf(v1, __shfl_xor_sync(0xffffffffu, v1, off));
            }
            if ((lane & 3) == 0) {
                const int r = ch * A_CH_ROWS + mt * 16 + (lane >> 2);
                pmax4[w * BROWS + r]     = v0;
                pmax4[w * BROWS + r + 8] = v1;
            }
        }
    };

    // tail variant: single m16 tile (rows 192..207)
    auto finish_tail = [&](float (&cc)[2][7][4]) {
        float r0 = NEG_BIG, r1 = NEG_BIG;
        #pragma unroll
        for (int i = 0; i < 7; ++i) {
            const int col0 = (w + 4 * i) * 8 + ((lane & 3) << 1);
            if (col0 < P) {
                r0 = fmaxf(r0, fmaxf(cc[0][i][0], cc[0][i][1]));
                r1 = fmaxf(r1, fmaxf(cc[0][i][2], cc[0][i][3]));
            }
        }
        #pragma unroll
        for (int off = 1; off <= 2; off <<= 1) {
            r0 = fmaxf(r0, __shfl_xor_sync(0xffffffffu, r0, off));
            r1 = fmaxf(r1, __shfl_xor_sync(0xffffffffu, r1, off));
        }
        if ((lane & 3) == 0) {
            const int r = 192 + (lane >> 2);
            pmax4[w * BROWS + r]     = r0;
            pmax4[w * BROWS + r + 8] = r1;
        }
    };

    auto reset_acc = [](float (&cc)[2][7][4]) {
        #pragma unroll
        for (int i = 0; i < 2; ++i)
            #pragma unroll
            for (int j = 0; j < 7; ++j)
                #pragma unroll
                for (int k = 0; k < 4; ++k) cc[i][j][k] = 0.0f;
    };

    float cacc[2][7][4];

    // ---- chunk 0: B streams in under compute via incremental waits ----
    reset_acc(cacc);
    chunk0_loop<0>(smb + SM_A, smb + SM_B, w, lane, cacc);
    finish_chunk(0, cacc);

    // ---- chunks 1..5: 32 rows each, double-buffered, barrier-free inner ----
    for (int ch = 1; ch < 6; ++ch) {
        __syncthreads();               // compute ch-1 done -> buf (ch+1)&1 free
        stage_a(ch + 1, (ch + 1) & 1); // stages chunks 2..6
        cp_wait_n<1>();                // chunk ch arrived
        __syncthreads();

        const uint32_t abase_ = smb + SM_A + (ch & 1) * A_BUF_SIZE;
        reset_acc(cacc);
        for (int kt = 0; kt < 6; ++kt)
            gemm_kt_mt2(abase_ + kt * A_KT_STRIDE, smb + SM_B + kt * B_KT_STRIDE,
                        w, lane, cacc);
        finish_chunk(ch, cacc);
    }

    // ---- tail chunk 6: compute only rows 192..207 (MT=1 body) ----
    {
        __syncthreads();
        cp_wait_n<0>();
        __syncthreads();
        const uint32_t abase_ = smb + SM_A + (6 & 1) * A_BUF_SIZE;
        reset_acc(cacc);
        for (int kt = 0; kt < 6; ++kt)
            gemm_kt_mt1(abase_ + kt * A_KT_STRIDE, smb + SM_B + kt * B_KT_STRIDE,
                        w, lane, cacc);
        finish_tail(cacc);
    }
    __syncthreads();

    // combine 4 warp-partials per query row, apply invq
    const float* invq = g_invq + (size_t)m * P;
    for (int r = tid; r < P; r += THREADS) {
        float v = fmaxf(fmaxf(pmax4[r], pmax4[BROWS + r]),
                        fmaxf(pmax4[2 * BROWS + r], pmax4[3 * BROWS + r]));
        pmax4[r] = v * invq[r];
    }
    __syncthreads();

    // warp 0: exact top-6 over pmax4[0..195]
    if (w == 0) {
        float v[7];
        #pragma unroll
        for (int k = 0; k < 7; ++k) {
            const int p = lane + 32 * k;
            v[k] = (p < P) ? pmax4[p] : NEG_BIG;
        }
        float total = 0.0f;
        for (int it = 0; it < 6; ++it) {
            float bv = NEG_BIG; int bk = 0;
            #pragma unroll
            for (int k = 0; k < 7; ++k)
                if (v[k] > bv) { bv = v[k]; bk = k; }
            int bi = lane + 32 * bk;
            #pragma unroll
            for (int off = 16; off; off >>= 1) {
                float ov = __shfl_xor_sync(0xffffffffu, bv, off);
                int   oi = __shfl_xor_sync(0xffffffffu, bi, off);
                if (ov > bv || (ov == bv && oi < bi)) { bv = ov; bi = oi; }
            }
            total += bv;
            if ((bi & 31) == lane) v[bi >> 5] = NEG_BIG;
        }
        if (lane == 0) out[m * NC + c] = scale_cls[0] * (total + bias[0]);
    }
}

// ---------------------------------------------------------------------------
extern "C" void kernel_launch(void* const* d_in, const int* in_sizes, int n_in,
                              void* d_out, int out_size) {
    const float* support   = (const float*)d_in[0];
    const float* query     = (const float*)d_in[1];
    const float* scale_cls = (const float*)d_in[2];
    const float* bias      = (const float*)d_in[3];
    float* out = (float*)d_out;

    // Stage 1: norms + bf16 conversion
    const int nrows = M_IMG * P + NC * P;
    const int blocks = (nrows * 32 + 255) / 256;
    stage_kernel<<<blocks, 256>>>(support, query);

    // Stage 2: fused HMMA GEMM + reductions (set attribute every call; capture-safe)
    cudaFuncSetAttribute(protonet_hmma_kernel,
                         cudaFuncAttributeMaxDynamicSharedMemorySize, SM_TOTAL);
    dim3 grid(NC, M_IMG);
    protonet_hmma_kernel<<<grid, THREADS, SM_TOTAL>>>(scale_cls, bias, out);
}

// round 16
// speedup vs baseline: 1.5044x; 1.5044x over previous
#include <cuda_runtime.h>
#include <cuda_bf16.h>
#include <cstdint>
#include <math.h>

// Shapes: support [5,196,384], query [512,196,384], out [1,512,5]
#define NC 5
#define M_IMG 512
#define P 196
#define D 384

#define NEG_BIG (-1.0e30f)

#define SROWS 256           // padded support rows per class in g_sbf (zero-init)
#define BROWS 224           // resident support rows (28 n8 tiles, uniform 7/warp)
#define NT8 28              // support n8 tiles
#define A_CH_ROWS 32        // query chunk rows (2 m16 tiles)
#define NCHUNK 7            // chunks 0..5 use 2 m16; chunk 6 computes 1 m16 (rows 192..207)

#define B_KT_STRIDE (BROWS * 128)     // 28672 B per k-tile
#define A_KT_STRIDE (A_CH_ROWS * 128) // 4096  B per k-tile
#define A_BUF_SIZE (A_CH_ROWS * 768)  // 24576 B per chunk buffer

// smem layout: [0..3584) pmax4[4][224] | [4096..53248) A bufs x2 | [53248..225280) B
#define SM_PM 0
#define SM_A 4096
#define SM_B 53248
#define SM_TOTAL 225280

#define THREADS 128
#define NSM 148
#define NTILE (NC * M_IMG)   // 2560

// ---------------- staged data (allocation-free: __device__ globals) -----------
// query: raw bf16 (+64 zero pad rows: chunk loads reach row 223 for m=511)
__device__ __align__(16) __nv_bfloat16 g_qbf[(M_IMG * P + 64) * D];
// support: L2-normalized bf16, padded to 256 rows/class (pad rows stay zero)
__device__ __align__(16) __nv_bfloat16 g_sbf[NC * SROWS * D];
// inverse L2 norm of each query row
__device__ float g_invq[M_IMG * P];

// ---------------- PTX helpers -------------------------------------------------
__device__ __forceinline__ uint32_t smem_u32(const void* p) {
    uint32_t a;
    asm("{ .reg .u64 t; cvta.to.shared.u64 t, %1; cvt.u32.u64 %0, t; }" : "=r"(a) : "l"(p));
    return a;
}
#define SW128(o) ((o) ^ (((o) >> 3) & 0x70))

__device__ __forceinline__ void cp_async16(uint32_t dst, const void* src) {
    asm volatile("cp.async.cg.shared.global [%0], [%1], 16;" :: "r"(dst), "l"(src));
}
__device__ __forceinline__ void cp_commit() { asm volatile("cp.async.commit_group;" ::: "memory"); }
template <int N>
__device__ __forceinline__ void cp_wait_n() {
    asm volatile("cp.async.wait_group %0;" :: "n"(N) : "memory");
}

#define LDSM_X4(r, addr) \
    asm volatile("ldmatrix.sync.aligned.m8n8.x4.shared.b16 {%0,%1,%2,%3}, [%4];" \
        : "=r"((r)[0]), "=r"((r)[1]), "=r"((r)[2]), "=r"((r)[3]) : "r"(addr))

#define LDSM_X2(r0, r1, addr) \
    asm volatile("ldmatrix.sync.aligned.m8n8.x2.shared.b16 {%0,%1}, [%2];" \
        : "=r"(r0), "=r"(r1) : "r"(addr))

#define MMA16816(c, a, b0, b1) \
    asm volatile("mma.sync.aligned.m16n8k16.row.col.f32.bf16.bf16.f32 " \
        "{%0,%1,%2,%3}, {%4,%5,%6,%7}, {%8,%9}, {%0,%1,%2,%3};" \
        : "+f"((c)[0]), "+f"((c)[1]), "+f"((c)[2]), "+f"((c)[3]) \
        : "r"((a)[0]), "r"((a)[1]), "r"((a)[2]), "r"((a)[3]), "r"(b0), "r"(b1))

// ---------------- Kernel 1: norms + bf16 staging ------------------------------
__global__ void stage_kernel(const float* __restrict__ support,
                             const float* __restrict__ query) {
    const int warp = (blockIdx.x * blockDim.x + threadIdx.x) >> 5;
    const int lane = threadIdx.x & 31;
    const int nq = M_IMG * P;
    const int nrows = nq + NC * P;
    if (warp >= nrows) return;

    const bool is_q = (warp < nq);
    const float* src = is_q ? (query + (size_t)warp * D)
                            : (support + (size_t)(warp - nq) * D);

    float4 v[3];
    float s = 0.0f;
    #pragma unroll
    for (int j = 0; j < 3; ++j) {
        v[j] = reinterpret_cast<const float4*>(src)[lane + 32 * j];
        s += v[j].x * v[j].x + v[j].y * v[j].y + v[j].z * v[j].z + v[j].w * v[j].w;
    }
    #pragma unroll
    for (int off = 16; off; off >>= 1) s += __shfl_xor_sync(0xffffffffu, s, off);
    const float inv = 1.0f / fmaxf(sqrtf(s), 1e-12f);

    if (is_q) {
        uint32_t* dst = reinterpret_cast<uint32_t*>(g_qbf + (size_t)warp * D);
        #pragma unroll
        for (int j = 0; j < 3; ++j) {
            const int k = lane + 32 * j;
            __nv_bfloat162 a = __floats2bfloat162_rn(v[j].x, v[j].y);
            __nv_bfloat162 b = __floats2bfloat162_rn(v[j].z, v[j].w);
            dst[2 * k]     = *reinterpret_cast<uint32_t*>(&a);
            dst[2 * k + 1] = *reinterpret_cast<uint32_t*>(&b);
        }
        if (lane == 0) g_invq[warp] = inv;
    } else {
        const int sr = warp - nq;
        const int c = sr / P, p = sr % P;
        uint32_t* dst = reinterpret_cast<uint32_t*>(g_sbf + ((size_t)c * SROWS + p) * D);
        #pragma unroll
        for (int j = 0; j < 3; ++j) {
            const int k = lane + 32 * j;
            __nv_bfloat162 a = __floats2bfloat162_rn(v[j].x * inv, v[j].y * inv);
            __nv_bfloat162 b = __floats2bfloat162_rn(v[j].z * inv, v[j].w * inv);
            dst[2 * k]     = *reinterpret_cast<uint32_t*>(&a);
            dst[2 * k + 1] = *reinterpret_cast<uint32_t*>(&b);
        }
    }
}

// ---------------- per-k-tile GEMM bodies (R14, byte-identical hot loop) -------
__device__ __forceinline__ void gemm_kt_mt2(uint32_t abase, uint32_t bbase,
                                            int w, int lane, float (&cacc)[2][7][4]) {
    const int l7 = lane & 7;
    const int a_row = (((lane >> 3) & 1) << 3) + l7;
    const int a_kb  = ((lane >> 4) & 1) << 4;
    const int sel16 = ((lane >> 3) & 1) << 4;
    #pragma unroll
    for (int k16 = 0; k16 < 4; ++k16) {
        const int kb = k16 * 32;
        uint32_t a[2][4];
        LDSM_X4(a[0], abase + SW128(a_row * 128 + kb + a_kb));
        LDSM_X4(a[1], abase + SW128((16 + a_row) * 128 + kb + a_kb));
        uint32_t b[7][2];
        #pragma unroll
        for (int i = 0; i < 7; ++i) {
            const int t = w + 4 * i;
            LDSM_X2(b[i][0], b[i][1],
                    bbase + SW128((t * 8 + l7) * 128 + kb + sel16));
        }
        #pragma unroll
        for (int mt = 0; mt < 2; ++mt)
            #pragma unroll
            for (int i = 0; i < 7; ++i)
                MMA16816(cacc[mt][i], a[mt], b[i][0], b[i][1]);
    }
}

__device__ __forceinline__ void gemm_kt_mt1(uint32_t abase, uint32_t bbase,
                                            int w, int lane, float (&cacc)[2][7][4]) {
    const int l7 = lane & 7;
    const int a_row = (((lane >> 3) & 1) << 3) + l7;
    const int a_kb  = ((lane >> 4) & 1) << 4;
    const int sel16 = ((lane >> 3) & 1) << 4;
    #pragma unroll
    for (int k16 = 0; k16 < 4; ++k16) {
        const int kb = k16 * 32;
        uint32_t a[4];
        LDSM_X4(a, abase + SW128(a_row * 128 + kb + a_kb));
        uint32_t b[7][2];
        #pragma unroll
        for (int i = 0; i < 7; ++i) {
            const int t = w + 4 * i;
            LDSM_X2(b[i][0], b[i][1],
                    bbase + SW128((t * 8 + l7) * 128 + kb + sel16));
        }
        #pragma unroll
        for (int i = 0; i < 7; ++i)
            MMA16816(cacc[0][i], a, b[i][0], b[i][1]);
    }
}

// chunk-0 loop for class-change tiles: B streams under compute.
// Pending after commits: {A0, B0..B5, A1}; at step KT allowed pending = 6-KT.
template <int KT>
__device__ __forceinline__ void chunk0_loop(uint32_t abase0, uint32_t bbase0,
                                            int w, int lane, float (&cacc)[2][7][4]) {
    if constexpr (KT < 6) {
        cp_wait_n<6 - KT>();
        __syncthreads();
        gemm_kt_mt2(abase0 + KT * A_KT_STRIDE, bbase0 + KT * B_KT_STRIDE,
                    w, lane, cacc);
        chunk0_loop<KT + 1>(abase0, bbase0, w, lane, cacc);
    }
}

// ---------------- Kernel 2: persistent class-major CTAs ------------------------
__global__ __launch_bounds__(THREADS, 1)
void protonet_hmma_kernel(const float* __restrict__ scale_cls,
                          const float* __restrict__ bias,
                          float* __restrict__ out) {
    extern __shared__ char sm[];
    const uint32_t smb = smem_u32(sm);
    float* pmax4 = reinterpret_cast<float*>(sm + SM_PM);   // [4][224]
    const int tid = threadIdx.x;
    const int w = tid >> 5;
    const int lane = tid & 31;

    // contiguous class-major tile range for this CTA (balanced 17/18)
    const int t0 = (int)(((long long)blockIdx.x * NTILE) / NSM);
    const int t1 = (int)(((long long)(blockIdx.x + 1) * NTILE) / NSM);

    const __nv_bfloat16* qbase = nullptr;

    auto stage_a = [&](int ch, int buf) {
        const uint32_t abase = smb + SM_A + buf * A_BUF_SIZE;
        #pragma unroll
        for (int idx = tid; idx < A_CH_ROWS * 8 * 6; idx += THREADS) {  // 1536 x 16B
            const int kt  = idx >> 8;              // /(32*8), compile-time shift
            const int rem = idx & 255;
            const int row = rem >> 3;
            const int cb  = (rem & 7) << 4;
            const void* src = qbase + (size_t)(ch * A_CH_ROWS + row) * D + kt * 64 + (cb >> 1);
            cp_async16(abase + kt * A_KT_STRIDE + SW128(row * 128 + cb), src);
        }
        cp_commit();
    };

    auto finish_chunk = [&](int ch, float (&cc)[2][7][4]) {
        float rmax[2][2];
        rmax[0][0] = rmax[0][1] = rmax[1][0] = rmax[1][1] = NEG_BIG;
        #pragma unroll
        for (int i = 0; i < 7; ++i) {
            const int col0 = (w + 4 * i) * 8 + ((lane & 3) << 1);
            if (col0 < P) {   // support col pair valid (196 is even)
                #pragma unroll
                for (int mt = 0; mt < 2; ++mt) {
                    rmax[mt][0] = fmaxf(rmax[mt][0], fmaxf(cc[mt][i][0], cc[mt][i][1]));
                    rmax[mt][1] = fmaxf(rmax[mt][1], fmaxf(cc[mt][i][2], cc[mt][i][3]));
                }
            }
        }
        #pragma unroll
        for (int mt = 0; mt < 2; ++mt) {
            float v0 = rmax[mt][0], v1 = rmax[mt][1];
            #pragma unroll
            for (int off = 1; off <= 2; off <<= 1) {
                v0 = fmaxf(v0, __shfl_xor_sync(0xffffffffu, v0, off));
                v1 = fmaxf(v1, __shfl_xor_sync(0xffffffffu, v1, off));
            }
            if ((lane & 3) == 0) {
                const int r = ch * A_CH_ROWS + mt * 16 + (lane >> 2);
                pmax4[w * BROWS + r]     = v0;
                pmax4[w * BROWS + r + 8] = v1;
            }
        }
    };

    auto finish_tail = [&](float (&cc)[2][7][4]) {
        float r0 = NEG_BIG, r1 = NEG_BIG;
        #pragma unroll
        for (int i = 0; i < 7; ++i) {
            const int col0 = (w + 4 * i) * 8 + ((lane & 3) << 1);
            if (col0 < P) {
                r0 = fmaxf(r0, fmaxf(cc[0][i][0], cc[0][i][1]));
                r1 = fmaxf(r1, fmaxf(cc[0][i][2], cc[0][i][3]));
            }
        }
        #pragma unroll
        for (int off = 1; off <= 2; off <<= 1) {
            r0 = fmaxf(r0, __shfl_xor_sync(0xffffffffu, r0, off));
            r1 = fmaxf(r1, __shfl_xor_sync(0xffffffffu, r1, off));
        }
        if ((lane & 3) == 0) {
            const int r = 192 + (lane >> 2);
            pmax4[w * BROWS + r]     = r0;
            pmax4[w * BROWS + r + 8] = r1;
        }
    };

    auto reset_acc = [](float (&cc)[2][7][4]) {
        #pragma unroll
        for (int i = 0; i < 2; ++i)
            #pragma unroll
            for (int j = 0; j < 7; ++j)
                #pragma unroll
                for (int k = 0; k < 4; ++k) cc[i][j][k] = 0.0f;
    };

    float cacc[2][7][4];
    int prev_c = -1;

    for (int t = t0; t < t1; ++t) {
        const int c = t >> 9;          // class (class-major order)
        const int m = t & 511;         // query image
        qbase = g_qbf + (size_t)m * P * D;
        const bool newB = (c != prev_c);
        prev_c = c;

        // ---- per-tile prologue ----
        stage_a(0, 0);
        if (newB) {
            const __nv_bfloat16* sbase = g_sbf + (size_t)c * SROWS * D;
            #pragma unroll
            for (int kt = 0; kt < 6; ++kt) {
                for (int idx = tid; idx < BROWS * 8; idx += THREADS) {  // 1792 x 16B
                    const int row = idx >> 3;
                    const int cb  = (idx & 7) << 4;
                    const void* src = sbase + (size_t)row * D + kt * 64 + (cb >> 1);
                    cp_async16(smb + SM_B + kt * B_KT_STRIDE + SW128(row * 128 + cb), src);
                }
                cp_commit();
            }
        }
        stage_a(1, 1);

        // ---- chunk 0 ----
        reset_acc(cacc);
        if (newB) {
            chunk0_loop<0>(smb + SM_A, smb + SM_B, w, lane, cacc);
        } else {
            cp_wait_n<1>();            // A0 arrived (A1 may be pending)
            __syncthreads();
            for (int kt = 0; kt < 6; ++kt)
                gemm_kt_mt2(smb + SM_A + kt * A_KT_STRIDE,
                            smb + SM_B + kt * B_KT_STRIDE, w, lane, cacc);
        }
        finish_chunk(0, cacc);

        // ---- chunks 1..5 ----
        for (int ch = 1; ch < 6; ++ch) {
            __syncthreads();               // compute ch-1 done -> buf (ch+1)&1 free
            stage_a(ch + 1, (ch + 1) & 1); // stages chunks 2..6
            cp_wait_n<1>();                // chunk ch arrived
            __syncthreads();

            const uint32_t abase_ = smb + SM_A + (ch & 1) * A_BUF_SIZE;
            reset_acc(cacc);
            for (int kt = 0; kt < 6; ++kt)
                gemm_kt_mt2(abase_ + kt * A_KT_STRIDE, smb + SM_B + kt * B_KT_STRIDE,
                            w, lane, cacc);
            finish_chunk(ch, cacc);
        }

        // ---- tail chunk 6 (rows 192..207, MT=1) ----
        {
            __syncthreads();
            cp_wait_n<0>();
            __syncthreads();
            const uint32_t abase_ = smb + SM_A + (6 & 1) * A_BUF_SIZE;
            reset_acc(cacc);
            for (int kt = 0; kt < 6; ++kt)
                gemm_kt_mt1(abase_ + kt * A_KT_STRIDE, smb + SM_B + kt * B_KT_STRIDE,
                            w, lane, cacc);
            finish_tail(cacc);
        }
        __syncthreads();

        // ---- epilogue: combine partials, x invq, top-6, write ----
        const float* invq = g_invq + (size_t)m * P;
        for (int r = tid; r < P; r += THREADS) {
            float v = fmaxf(fmaxf(pmax4[r], pmax4[BROWS + r]),
                            fmaxf(pmax4[2 * BROWS + r], pmax4[3 * BROWS + r]));
            pmax4[r] = v * invq[r];
        }
        __syncthreads();

        if (w == 0) {
            float v[7];
            #pragma unroll
            for (int k = 0; k < 7; ++k) {
                const int p = lane + 32 * k;
                v[k] = (p < P) ? pmax4[p] : NEG_BIG;
            }
            float total = 0.0f;
            for (int it = 0; it < 6; ++it) {
                float bv = NEG_BIG; int bk = 0;
                #pragma unroll
                for (int k = 0; k < 7; ++k)
                    if (v[k] > bv) { bv = v[k]; bk = k; }
                int bi = lane + 32 * bk;
                #pragma unroll
                for (int off = 16; off; off >>= 1) {
                    float ov = __shfl_xor_sync(0xffffffffu, bv, off);
                    int   oi = __shfl_xor_sync(0xffffffffu, bi, off);
                    if (ov > bv || (ov == bv && oi < bi)) { bv = ov; bi = oi; }
                }
                total += bv;
                if ((bi & 31) == lane) v[bi >> 5] = NEG_BIG;
            }
            if (lane == 0) out[m * NC + c] = scale_cls[0] * (total + bias[0]);
        }
        __syncthreads();   // pmax4 & A bufs safe before next tile's stores
    }
}

// ---------------------------------------------------------------------------
extern "C" void kernel_launch(void* const* d_in, const int* in_sizes, int n_in,
                              void* d_out, int out_size) {
    const float* support   = (const float*)d_in[0];
    const float* query     = (const float*)d_in[1];
    const float* scale_cls = (const float*)d_in[2];
    const float* bias      = (const float*)d_in[3];
    float* out = (float*)d_out;

    // Stage 1: norms + bf16 conversion
    const int nrows = M_IMG * P + NC * P;
    const int blocks = (nrows * 32 + 255) / 256;
    stage_kernel<<<blocks, 256>>>(support, query);

    // Stage 2: persistent fused HMMA GEMM + reductions
    cudaFuncSetAttribute(protonet_hmma_kernel,
                         cudaFuncAttributeMaxDynamicSharedMemorySize, SM_TOTAL);
    protonet_hmma_kernel<<<NSM, THREADS, SM_TOTAL>>>(scale_cls, bias, out);
}